// round 1
// baseline (speedup 1.0000x reference)
#include <cuda_runtime.h>
#include <math.h>

#define B_ 2
#define C_ 10
#define N_ 100
#define M_ 50
#define HW 9216      // 96*96
#define HPWP 576     // 24*24
#define TN 10        // n-tile per block in dot kernel
#define KSPLIT 12
#define KCHUNK 768   // 9216/12
#define KK 64

#define TWO_PI_F 6.2831854820251465f
#define PI_F 3.1415927410125732f

// ---------------- scratch (device globals; no allocation allowed) ----------
__device__ float g_P[B_ * N_ * HW];     // resized pred mask
__device__ float g_G[B_ * N_ * HW];     // f1 - f0 per pixel
__device__ float g_Sp[B_ * N_];         // sum of p per (b,n)
__device__ float g_F0[B_ * N_];         // sum of f0 per (b,n)
__device__ float g_St[B_ * M_];         // sum of t per (b,m)
__device__ float g_part1[B_ * KSPLIT * N_ * M_];  // k-split partial of <t,p>
__device__ float g_part2[B_ * KSPLIT * N_ * M_];  // k-split partial of <t,g>

// ---------------- helpers ----------------
__device__ __forceinline__ float blockReduceSum(float v, float* sh) {
    // 256 threads
    int lane = threadIdx.x & 31;
    int wid = threadIdx.x >> 5;
    #pragma unroll
    for (int o = 16; o > 0; o >>= 1) v += __shfl_down_sync(0xffffffffu, v, o);
    if (lane == 0) sh[wid] = v;
    __syncthreads();
    v = (threadIdx.x < 8) ? sh[threadIdx.x] : 0.0f;
    if (wid == 0) {
        #pragma unroll
        for (int o = 4; o > 0; o >>= 1) v += __shfl_down_sync(0xffffffffu, v, o);
    }
    return v;  // valid in thread 0
}

__device__ __forceinline__ float sigmoidf_(float x) {
    return 1.0f / (1.0f + expf(-x));
}

// ---------------- kernel 1: bilinear resize 24->96 + derive P, G, Sp, F0 ----
__global__ void k_resize(const float* __restrict__ pred_mask) {
    int bn = blockIdx.x;  // 0..199
    __shared__ float sm[HPWP];
    __shared__ float red[8];
    const float* src = pred_mask + bn * HPWP;
    for (int i = threadIdx.x; i < HPWP; i += 256) sm[i] = src[i];
    __syncthreads();

    float* Pout = g_P + (size_t)bn * HW;
    float* Gout = g_G + (size_t)bn * HW;
    float sp = 0.0f, sf0 = 0.0f;

    for (int i = threadIdx.x; i < HW; i += 256) {
        int y = i / 96, x = i - y * 96;
        // jax half-pixel: s = (out+0.5)*scale - 0.5, scale=0.25
        float sy = y * 0.25f - 0.375f;
        float sx = x * 0.25f - 0.375f;
        float fy = floorf(sy), fx = floorf(sx);
        float wy = sy - fy, wx = sx - fx;
        int iy = (int)fy, ix = (int)fx;
        int iy0 = max(iy, 0), iy1 = min(iy + 1, 23);
        int ix0 = max(ix, 0), ix1 = min(ix + 1, 23);
        float v00 = sm[iy0 * 24 + ix0], v01 = sm[iy0 * 24 + ix1];
        float v10 = sm[iy1 * 24 + ix0], v11 = sm[iy1 * 24 + ix1];
        float top = v00 + wx * (v01 - v00);
        float bot = v10 + wx * (v11 - v10);
        float p = top + wy * (bot - top);

        float pc = fminf(fmaxf(p, 0.001f), 0.999f);
        float omc = 1.0f - pc;
        float f1 = 0.25f * (-logf(pc)) * omc * omc;
        float f0 = 0.75f * (-logf(omc)) * pc * pc;
        Pout[i] = p;
        Gout[i] = f1 - f0;
        sp += fabsf(p);
        sf0 += f0;
    }
    float tsp = blockReduceSum(sp, red);
    __syncthreads();
    float tsf = blockReduceSum(sf0, red);
    if (threadIdx.x == 0) {
        g_Sp[bn] = tsp;
        g_F0[bn] = tsf;
    }
}

// ---------------- kernel 2: St per (b,m) ----------------
__global__ void k_st(const float* __restrict__ tmask) {
    int bm = blockIdx.x;  // 0..99
    __shared__ float red[8];
    const float* src = tmask + (size_t)bm * HW;
    float s = 0.0f;
    for (int i = threadIdx.x; i < HW; i += 256) s += fabsf(src[i]);
    float t = blockReduceSum(s, red);
    if (threadIdx.x == 0) g_St[bm] = t;
}

// ---------------- kernel 3: the two dot products (tiled, k-split) ----------
__global__ void __launch_bounds__(256) k_dots(const float* __restrict__ tmask) {
    int nt = blockIdx.x;   // 0..9
    int ks = blockIdx.y;   // 0..11
    int b  = blockIdx.z;   // 0..1

    __shared__ float sh_t[M_][KK + 1];
    __shared__ float sh_p[TN][KK + 1];
    __shared__ float sh_g[TN][KK + 1];

    int tid = threadIdx.x;
    int m = tid % 50;
    int ng = tid / 50;       // 0..5 (5 -> inactive)
    bool active = tid < 250;

    const float* Tbase = tmask + (size_t)b * M_ * HW;
    const float* Pbase = g_P + (size_t)(b * N_ + nt * TN) * HW;
    const float* Gbase = g_G + (size_t)(b * N_ + nt * TN) * HW;

    float a1_0 = 0.f, a1_1 = 0.f, a2_0 = 0.f, a2_1 = 0.f;

    int kbeg = ks * KCHUNK;
    for (int k0 = kbeg; k0 < kbeg + KCHUNK; k0 += KK) {
        // load T tile: 50*KK
        for (int e = tid; e < M_ * KK; e += 256) {
            int mm = e / KK, kk = e - mm * KK;
            sh_t[mm][kk] = Tbase[(size_t)mm * HW + k0 + kk];
        }
        // load P,G tiles: TN*KK each
        for (int e = tid; e < TN * KK; e += 256) {
            int nn = e / KK, kk = e - nn * KK;
            sh_p[nn][kk] = Pbase[(size_t)nn * HW + k0 + kk];
            sh_g[nn][kk] = Gbase[(size_t)nn * HW + k0 + kk];
        }
        __syncthreads();
        if (active) {
            #pragma unroll 16
            for (int kk = 0; kk < KK; kk++) {
                float tv = sh_t[m][kk];
                a1_0 += tv * sh_p[ng][kk];
                a1_1 += tv * sh_p[ng + 5][kk];
                a2_0 += tv * sh_g[ng][kk];
                a2_1 += tv * sh_g[ng + 5][kk];
            }
        }
        __syncthreads();
    }

    if (active) {
        int n0 = nt * TN + ng;
        int n1 = n0 + 5;
        size_t base = (size_t)(b * KSPLIT + ks) * N_;
        g_part1[(base + n0) * M_ + m] = a1_0;
        g_part1[(base + n1) * M_ + m] = a1_1;
        g_part2[(base + n0) * M_ + m] = a2_0;
        g_part2[(base + n1) * M_ + m] = a2_1;
    }
}

// ---------------- kernel 4: assemble final cost ----------------
__global__ void k_assemble(const float* __restrict__ pred_prob,
                           const float* __restrict__ pred_mom,
                           const int*   __restrict__ tcls,
                           const float* __restrict__ tmom,
                           float* __restrict__ out) {
    int idx = blockIdx.x * blockDim.x + threadIdx.x;
    if (idx >= B_ * N_ * M_) return;
    int m = idx % M_;
    int n = (idx / M_) % N_;
    int b = idx / (N_ * M_);

    int cls = tcls[b * M_ + m];
    if (cls <= 0) { out[idx] = 100000.0f; return; }

    float dot1 = 0.f, dot2 = 0.f;
    #pragma unroll
    for (int ks = 0; ks < KSPLIT; ks++) {
        size_t base = ((size_t)(b * KSPLIT + ks) * N_ + n) * M_ + m;
        dot1 += g_part1[base];
        dot2 += g_part2[base];
    }

    float Sp = g_Sp[b * N_ + n];
    float F0s = g_F0[b * N_ + n];
    float St = g_St[b * M_ + m];
    float pos = Sp + St;
    float cost_dice = 1.0f - 2.0f * dot1 / (pos + 0.001f);
    float cost_focal = (F0s + dot2) * (1.0f / (float)HW);
    float cost_class = -pred_prob[((size_t)b * C_ + cls) * N_ + n];

    // momentum: calc_bbox(pred_momentum)
    const float* pmv = pred_mom + (size_t)(b * N_ + n) * 4;
    float p0 = expf(fminf(pmv[0], 10.0f));
    float p1 = sigmoidf_(pmv[1]) * TWO_PI_F;
    float p2 = sigmoidf_(pmv[2]) * TWO_PI_F;
    float p3 = expf(fminf(pmv[3], 10.0f));
    const float* tmv = tmom + (size_t)(b * M_ + m) * 4;
    float t0 = tmv[0], t1 = tmv[1], t2 = tmv[2], t3 = tmv[3];

    // momentum L1
    float pe = (t2 - p2 > PI_F) ? TWO_PI_F : 0.0f;  // added to pred phi
    float te = (p2 - t2 > PI_F) ? TWO_PI_F : 0.0f;  // added to tgt phi
    float l1 = (fabsf(p0 / (t0 + 0.001f) - 1.0f)
              + fabsf(p1 / (t1 + 0.001f) - 1.0f)
              + fabsf((p2 + pe) / (t2 + te + 0.001f) - 1.0f)
              + fabsf(p3 / (t3 + 0.001f) - 1.0f)) * 0.25f;

    // eiou: w1=pt, x1=rap, y1=phi, h1=m
    float w1 = p0, x1 = p1, y1 = p2, h1 = p3;
    float w2 = t0, x2 = t1, y2 = t2, h2 = t3;
    float y1e = (y2 - y1 > PI_F) ? TWO_PI_F : 0.0f;
    float y2e = (y1 - y2 > PI_F) ? TWO_PI_F : 0.0f;
    y1 += y1e;
    y2 += y2e;
    float r1 = x1 + w1 * 0.5f, l1b = x1 - w1 * 0.5f;
    float r2 = x2 + w2 * 0.5f, l2b = x2 - w2 * 0.5f;
    float u1 = y1 + h1 * 0.5f, d1 = y1 - h1 * 0.5f;
    float u2 = y2 + h2 * 0.5f, d2 = y2 - h2 * 0.5f;
    float w = fminf(r1, r2) - fmaxf(l1b, l2b);
    float h = fminf(u1, u2) - fmaxf(d1, d2);
    float iou = (w > 0.0f && h > 0.0f)
                ? (w * h) / (w1 * h1 + w2 * h2 - w * h + 0.001f) : 0.0f;
    float cw = fmaxf(r1, r2) - fminf(l1b, l2b);
    float ch = fmaxf(u1, u2) - fminf(d1, d2);
    float cw2 = cw * cw, ch2 = ch * ch;
    float dw = w1 - w2, dh = h1 - h2;
    float rho_w = dw * dw / (cw2 + 0.001f);
    float rho_h = dh * dh / (ch2 + 0.001f);
    float dx = x1 - x2, dy = y1 - y2;
    float rho_d = (dx * dx + dy * dy) / (cw2 + ch2 + 0.001f);
    float ce = 1.0f - iou + rho_d + rho_w + rho_h;

    out[idx] = 0.25f * cost_focal + 0.75f * cost_dice + cost_class
             + 0.8f * l1 + 0.2f * ce;
}

extern "C" void kernel_launch(void* const* d_in, const int* in_sizes, int n_in,
                              void* d_out, int out_size) {
    const float* pred_prob = (const float*)d_in[0];   // (2,10,100)
    const float* pred_mask = (const float*)d_in[1];   // (2,100,24,24)
    const float* pred_mom  = (const float*)d_in[2];   // (2,100,4)
    const int*   tcls      = (const int*)d_in[3];     // (2,50)
    const float* tmask     = (const float*)d_in[4];   // (2,50,96,96)
    const float* tmom      = (const float*)d_in[5];   // (2,50,4)
    float* out = (float*)d_out;                       // (2,100,50)

    k_resize<<<B_ * N_, 256>>>(pred_mask);
    k_st<<<B_ * M_, 256>>>(tmask);
    dim3 grid(N_ / TN, KSPLIT, B_);
    k_dots<<<grid, 256>>>(tmask);
    k_assemble<<<(B_ * N_ * M_ + 255) / 256, 256>>>(pred_prob, pred_mom, tcls, tmom, out);
}

// round 4
// speedup vs baseline: 1.9969x; 1.9969x over previous
#include <cuda_runtime.h>
#include <math.h>

#define B_ 2
#define C_ 10
#define N_ 100
#define M_ 50
#define HW 9216      // 96*96
#define HPWP 576     // 24*24
#define KSPLIT 36
#define KCHUNK 256   // 9216/36
#define KK 32        // k-stage in shared
#define STR 34       // row stride (floats): 8B-aligned rows, 17 mod 16 spread for LDS.64
#define NTILE 50     // n per block in dot kernel

#define TWO_PI_F 6.2831854820251465f
#define PI_F 3.1415927410125732f

typedef unsigned long long ull;

// ---------------- scratch ----------------
__device__ __align__(16) float g_P[B_ * N_ * HW];
__device__ __align__(16) float g_G[B_ * N_ * HW];
__device__ __align__(16) float g_Sp[B_ * N_];
__device__ __align__(16) float g_F0[B_ * N_];
__device__ __align__(16) float g_St[B_ * M_];
__device__ __align__(16) float g_part1[B_ * KSPLIT * N_ * M_];  // [b][ks][n*50+m]
__device__ __align__(16) float g_part2[B_ * KSPLIT * N_ * M_];

#define FMA2(d, a, b, c) \
    asm("fma.rn.f32x2 %0, %1, %2, %3;" : "=l"(d) : "l"(a), "l"(b), "l"(c))

// ---------------- helpers ----------------
__device__ __forceinline__ float blockReduceSum(float v, float* sh) {
    int lane = threadIdx.x & 31;
    int wid = threadIdx.x >> 5;
    #pragma unroll
    for (int o = 16; o > 0; o >>= 1) v += __shfl_down_sync(0xffffffffu, v, o);
    if (lane == 0) sh[wid] = v;
    __syncthreads();
    v = (threadIdx.x < 8) ? sh[threadIdx.x] : 0.0f;
    if (wid == 0) {
        #pragma unroll
        for (int o = 4; o > 0; o >>= 1) v += __shfl_down_sync(0xffffffffu, v, o);
    }
    return v;
}

// ---------------- kernel 1: resize 24->96 + derive P, G, Sp, F0 ------------
__global__ void k_resize(const float* __restrict__ pred_mask) {
    int bn = blockIdx.x;  // 0..199
    __shared__ float sm[HPWP];
    __shared__ float red[8];
    const float* src = pred_mask + bn * HPWP;
    for (int i = threadIdx.x; i < HPWP; i += 256) sm[i] = src[i];
    __syncthreads();

    float* Pout = g_P + (size_t)bn * HW;
    float* Gout = g_G + (size_t)bn * HW;
    float sp = 0.0f, sf0 = 0.0f;

    for (int i = threadIdx.x; i < HW; i += 256) {
        int y = i / 96, x = i - y * 96;
        float sy = y * 0.25f - 0.375f;
        float sx = x * 0.25f - 0.375f;
        float fy = floorf(sy), fx = floorf(sx);
        float wy = sy - fy, wx = sx - fx;
        int iy = (int)fy, ix = (int)fx;
        int iy0 = max(iy, 0), iy1 = min(iy + 1, 23);
        int ix0 = max(ix, 0), ix1 = min(ix + 1, 23);
        float v00 = sm[iy0 * 24 + ix0], v01 = sm[iy0 * 24 + ix1];
        float v10 = sm[iy1 * 24 + ix0], v11 = sm[iy1 * 24 + ix1];
        float top = v00 + wx * (v01 - v00);
        float bot = v10 + wx * (v11 - v10);
        float p = top + wy * (bot - top);

        float pc = fminf(fmaxf(p, 0.001f), 0.999f);
        float omc = 1.0f - pc;
        float f1 = 0.25f * (-__logf(pc)) * omc * omc;
        float f0 = 0.75f * (-__logf(omc)) * pc * pc;
        Pout[i] = p;
        Gout[i] = f1 - f0;
        sp += fabsf(p);
        sf0 += f0;
    }
    float tsp = blockReduceSum(sp, red);
    __syncthreads();
    float tsf = blockReduceSum(sf0, red);
    if (threadIdx.x == 0) {
        g_Sp[bn] = tsp;
        g_F0[bn] = tsf;
    }
}

// ---------------- kernel 2: St per (b,m) ----------------
__global__ void k_st(const float* __restrict__ tmask) {
    int bm = blockIdx.x;
    __shared__ float red[8];
    const float* src = tmask + (size_t)bm * HW;
    float s = 0.0f;
    for (int i = threadIdx.x; i < HW; i += 256) s += fabsf(src[i]);
    float t = blockReduceSum(s, red);
    if (threadIdx.x == 0) g_St[bm] = t;
}

// ---------------- kernel 3: dots via f32x2 FMA, register-tiled -------------
// grid (2 n-tiles, KSPLIT, B), block 256 (250 active)
// thread tile: 5 m x 2 n x 2 dots -> 20 f32x2 accumulators
__global__ void __launch_bounds__(256) k_dots(const float* __restrict__ tmask) {
    int nt = blockIdx.x;   // 0..1
    int ks = blockIdx.y;   // 0..KSPLIT-1
    int b  = blockIdx.z;

    __shared__ __align__(16) float sh_t[M_ * STR];
    __shared__ __align__(16) float sh_p[NTILE * STR];
    __shared__ __align__(16) float sh_g[NTILE * STR];

    int tid = threadIdx.x;
    int mg = tid % 10;        // m0 = mg*5
    int ng = tid / 10;        // 0..24 (>=25 inactive); n0 = ng*2
    bool active = tid < 250;
    int m0 = mg * 5;
    int n0 = ng * 2;

    const float* Tbase = tmask + (size_t)b * M_ * HW;
    const float* Pbase = g_P + (size_t)(b * N_ + nt * NTILE) * HW;
    const float* Gbase = g_G + (size_t)(b * N_ + nt * NTILE) * HW;

    ull a1[5][2], a2[5][2];
    #pragma unroll
    for (int i = 0; i < 5; i++)
        #pragma unroll
        for (int j = 0; j < 2; j++) { a1[i][j] = 0ULL; a2[i][j] = 0ULL; }

    const ull* sh_t2 = (const ull*)sh_t;
    const ull* sh_p2 = (const ull*)sh_p;
    const ull* sh_g2 = (const ull*)sh_g;

    int kbeg = ks * KCHUNK;
    for (int k0 = kbeg; k0 < kbeg + KCHUNK; k0 += KK) {
        // load tiles: T/P/G 50x32 each. LDG.128 from global (16B-aligned),
        // STS.64 x2 into shared (row stride 136B is only 8B-aligned).
        #pragma unroll
        for (int e = tid; e < 400; e += 256) {
            int row = e >> 3, c4 = (e & 7) << 2;
            float4 v = *(const float4*)(Tbase + (size_t)row * HW + k0 + c4);
            float* d = sh_t + row * STR + c4;
            *(float2*)(d)     = make_float2(v.x, v.y);
            *(float2*)(d + 2) = make_float2(v.z, v.w);
        }
        #pragma unroll
        for (int e = tid; e < 400; e += 256) {
            int row = e >> 3, c4 = (e & 7) << 2;
            float4 v = *(const float4*)(Pbase + (size_t)row * HW + k0 + c4);
            float* d = sh_p + row * STR + c4;
            *(float2*)(d)     = make_float2(v.x, v.y);
            *(float2*)(d + 2) = make_float2(v.z, v.w);
            float4 w = *(const float4*)(Gbase + (size_t)row * HW + k0 + c4);
            float* e2 = sh_g + row * STR + c4;
            *(float2*)(e2)     = make_float2(w.x, w.y);
            *(float2*)(e2 + 2) = make_float2(w.z, w.w);
        }
        __syncthreads();

        if (active) {
            #pragma unroll
            for (int kp = 0; kp < KK / 2; kp++) {
                ull tv[5], pv[2], gv[2];
                #pragma unroll
                for (int i = 0; i < 5; i++) tv[i] = sh_t2[(m0 + i) * (STR / 2) + kp];
                #pragma unroll
                for (int j = 0; j < 2; j++) {
                    pv[j] = sh_p2[(n0 + j) * (STR / 2) + kp];
                    gv[j] = sh_g2[(n0 + j) * (STR / 2) + kp];
                }
                #pragma unroll
                for (int i = 0; i < 5; i++) {
                    #pragma unroll
                    for (int j = 0; j < 2; j++) {
                        FMA2(a1[i][j], tv[i], pv[j], a1[i][j]);
                        FMA2(a2[i][j], tv[i], gv[j], a2[i][j]);
                    }
                }
            }
        }
        __syncthreads();
    }

    if (active) {
        size_t base = (size_t)(b * KSPLIT + ks) * (N_ * M_);
        #pragma unroll
        for (int i = 0; i < 5; i++) {
            #pragma unroll
            for (int j = 0; j < 2; j++) {
                int n = nt * NTILE + n0 + j;
                int m = m0 + i;
                float2 v1 = *(float2*)&a1[i][j];
                float2 v2 = *(float2*)&a2[i][j];
                g_part1[base + n * M_ + m] = v1.x + v1.y;
                g_part2[base + n * M_ + m] = v2.x + v2.y;
            }
        }
    }
}

// ---------------- kernel 4: assemble ----------------
__global__ void k_assemble(const float* __restrict__ pred_prob,
                           const float* __restrict__ pred_mom,
                           const int*   __restrict__ tcls,
                           const float* __restrict__ tmom,
                           float* __restrict__ out) {
    int idx = blockIdx.x * blockDim.x + threadIdx.x;
    if (idx >= B_ * N_ * M_) return;
    int m = idx % M_;
    int n = (idx / M_) % N_;
    int b = idx / (N_ * M_);

    int cls = tcls[b * M_ + m];
    if (cls <= 0) { out[idx] = 100000.0f; return; }

    int nm = n * M_ + m;
    float dot1 = 0.f, dot2 = 0.f;
    #pragma unroll
    for (int ks = 0; ks < KSPLIT; ks++) {
        size_t base = (size_t)(b * KSPLIT + ks) * (N_ * M_) + nm;
        dot1 += g_part1[base];
        dot2 += g_part2[base];
    }

    float Sp = g_Sp[b * N_ + n];
    float F0s = g_F0[b * N_ + n];
    float St = g_St[b * M_ + m];
    float pos = Sp + St;
    float cost_dice = 1.0f - 2.0f * dot1 / (pos + 0.001f);
    float cost_focal = (F0s + dot2) * (1.0f / (float)HW);
    float cost_class = -pred_prob[((size_t)b * C_ + cls) * N_ + n];

    const float* pmv = pred_mom + (size_t)(b * N_ + n) * 4;
    float p0 = __expf(fminf(pmv[0], 10.0f));
    float p1 = TWO_PI_F / (1.0f + __expf(-pmv[1]));
    float p2 = TWO_PI_F / (1.0f + __expf(-pmv[2]));
    float p3 = __expf(fminf(pmv[3], 10.0f));
    const float* tmv = tmom + (size_t)(b * M_ + m) * 4;
    float t0 = tmv[0], t1 = tmv[1], t2 = tmv[2], t3 = tmv[3];

    float pe = (t2 - p2 > PI_F) ? TWO_PI_F : 0.0f;
    float te = (p2 - t2 > PI_F) ? TWO_PI_F : 0.0f;
    float l1 = (fabsf(p0 / (t0 + 0.001f) - 1.0f)
              + fabsf(p1 / (t1 + 0.001f) - 1.0f)
              + fabsf((p2 + pe) / (t2 + te + 0.001f) - 1.0f)
              + fabsf(p3 / (t3 + 0.001f) - 1.0f)) * 0.25f;

    float w1 = p0, x1 = p1, y1 = p2, h1 = p3;
    float w2 = t0, x2 = t1, y2 = t2, h2 = t3;
    float y1e = (y2 - y1 > PI_F) ? TWO_PI_F : 0.0f;
    float y2e = (y1 - y2 > PI_F) ? TWO_PI_F : 0.0f;
    y1 += y1e;
    y2 += y2e;
    float r1 = x1 + w1 * 0.5f, l1b = x1 - w1 * 0.5f;
    float r2 = x2 + w2 * 0.5f, l2b = x2 - w2 * 0.5f;
    float u1 = y1 + h1 * 0.5f, d1 = y1 - h1 * 0.5f;
    float u2 = y2 + h2 * 0.5f, d2 = y2 - h2 * 0.5f;
    float w = fminf(r1, r2) - fmaxf(l1b, l2b);
    float h = fminf(u1, u2) - fmaxf(d1, d2);
    float iou = (w > 0.0f && h > 0.0f)
                ? (w * h) / (w1 * h1 + w2 * h2 - w * h + 0.001f) : 0.0f;
    float cw = fmaxf(r1, r2) - fminf(l1b, l2b);
    float ch = fmaxf(u1, u2) - fminf(d1, d2);
    float cw2 = cw * cw, ch2 = ch * ch;
    float dw = w1 - w2, dh = h1 - h2;
    float rho_w = dw * dw / (cw2 + 0.001f);
    float rho_h = dh * dh / (ch2 + 0.001f);
    float dx = x1 - x2, dy = y1 - y2;
    float rho_d = (dx * dx + dy * dy) / (cw2 + ch2 + 0.001f);
    float ce = 1.0f - iou + rho_d + rho_w + rho_h;

    out[idx] = 0.25f * cost_focal + 0.75f * cost_dice + cost_class
             + 0.8f * l1 + 0.2f * ce;
}

extern "C" void kernel_launch(void* const* d_in, const int* in_sizes, int n_in,
                              void* d_out, int out_size) {
    const float* pred_prob = (const float*)d_in[0];
    const float* pred_mask = (const float*)d_in[1];
    const float* pred_mom  = (const float*)d_in[2];
    const int*   tcls      = (const int*)d_in[3];
    const float* tmask     = (const float*)d_in[4];
    const float* tmom      = (const float*)d_in[5];
    float* out = (float*)d_out;

    k_resize<<<B_ * N_, 256>>>(pred_mask);
    k_st<<<B_ * M_, 256>>>(tmask);
    dim3 grid(N_ / NTILE, KSPLIT, B_);
    k_dots<<<grid, 256>>>(tmask);
    k_assemble<<<(B_ * N_ * M_ + 255) / 256, 256>>>(pred_prob, pred_mom, tcls, tmom, out);
}

// round 5
// speedup vs baseline: 2.0795x; 1.0414x over previous
#include <cuda_runtime.h>
#include <math.h>

#define B_ 2
#define C_ 10
#define N_ 100
#define M_ 50
#define HW 9216      // 96*96
#define HPWP 576     // 24*24
#define KSPLIT 72
#define KCHUNK 128   // 9216/72
#define KK 32        // k-stage in shared
#define STR 34       // row stride (floats): 8B-aligned rows, conflict-free LDS.64
#define TWO_PI_F 6.2831854820251465f
#define PI_F 3.1415927410125732f

typedef unsigned long long ull;

// ---------------- scratch ----------------
__device__ __align__(16) float g_P[B_ * N_ * HW];
__device__ __align__(16) float g_G[B_ * N_ * HW];
__device__ __align__(16) float g_Sp[B_ * N_];
__device__ __align__(16) float g_F0[B_ * N_];
__device__ __align__(16) float g_St[B_ * M_];
// layout: [b][n][m][ks]  (ks contiguous -> vector loads in assemble)
__device__ __align__(16) float g_part1[B_ * N_ * M_ * KSPLIT];
__device__ __align__(16) float g_part2[B_ * N_ * M_ * KSPLIT];

#define FMA2(d, a, b, c) \
    asm("fma.rn.f32x2 %0, %1, %2, %3;" : "=l"(d) : "l"(a), "l"(b), "l"(c))

// ---------------- helpers ----------------
__device__ __forceinline__ float blockReduceSum(float v, float* sh) {
    int lane = threadIdx.x & 31;
    int wid = threadIdx.x >> 5;
    #pragma unroll
    for (int o = 16; o > 0; o >>= 1) v += __shfl_down_sync(0xffffffffu, v, o);
    if (lane == 0) sh[wid] = v;
    __syncthreads();
    v = (threadIdx.x < 8) ? sh[threadIdx.x] : 0.0f;
    if (wid == 0) {
        #pragma unroll
        for (int o = 4; o > 0; o >>= 1) v += __shfl_down_sync(0xffffffffu, v, o);
    }
    return v;
}

// ---------------- kernel 1: resize 24->96 + derive P, G, Sp, F0 ------------
__global__ void k_resize(const float* __restrict__ pred_mask) {
    int bn = blockIdx.x;  // 0..199
    __shared__ float sm[HPWP];
    __shared__ float red[8];
    const float* src = pred_mask + bn * HPWP;
    for (int i = threadIdx.x; i < HPWP; i += 256) sm[i] = src[i];
    __syncthreads();

    float* Pout = g_P + (size_t)bn * HW;
    float* Gout = g_G + (size_t)bn * HW;
    float sp = 0.0f, sf0 = 0.0f;

    for (int i = threadIdx.x; i < HW; i += 256) {
        int y = i / 96, x = i - y * 96;
        float sy = y * 0.25f - 0.375f;
        float sx = x * 0.25f - 0.375f;
        float fy = floorf(sy), fx = floorf(sx);
        float wy = sy - fy, wx = sx - fx;
        int iy = (int)fy, ix = (int)fx;
        int iy0 = max(iy, 0), iy1 = min(iy + 1, 23);
        int ix0 = max(ix, 0), ix1 = min(ix + 1, 23);
        float v00 = sm[iy0 * 24 + ix0], v01 = sm[iy0 * 24 + ix1];
        float v10 = sm[iy1 * 24 + ix0], v11 = sm[iy1 * 24 + ix1];
        float top = v00 + wx * (v01 - v00);
        float bot = v10 + wx * (v11 - v10);
        float p = top + wy * (bot - top);

        float pc = fminf(fmaxf(p, 0.001f), 0.999f);
        float omc = 1.0f - pc;
        float f1 = 0.25f * (-__logf(pc)) * omc * omc;
        float f0 = 0.75f * (-__logf(omc)) * pc * pc;
        Pout[i] = p;
        Gout[i] = f1 - f0;
        sp += fabsf(p);
        sf0 += f0;
    }
    float tsp = blockReduceSum(sp, red);
    __syncthreads();
    float tsf = blockReduceSum(sf0, red);
    if (threadIdx.x == 0) {
        g_Sp[bn] = tsp;
        g_F0[bn] = tsf;
    }
}

// ---------------- kernel 2: St per (b,m) ----------------
__global__ void k_st(const float* __restrict__ tmask) {
    int bm = blockIdx.x;
    __shared__ float red[8];
    const float* src = tmask + (size_t)bm * HW;
    float s = 0.0f;
    for (int i = threadIdx.x; i < HW; i += 256) s += fabsf(src[i]);
    float t = blockReduceSum(s, red);
    if (threadIdx.x == 0) g_St[bm] = t;
}

// ---------------- kernel 3: dots, 512 threads, all-N per block -------------
// grid (KSPLIT, B). thread tile: 5m x 2n x 2 dots. 500 active threads cover
// 50m x 100n. 4 warps/SMSP for latency hiding.
__global__ void __launch_bounds__(512) k_dots(const float* __restrict__ tmask) {
    int ks = blockIdx.x;   // 0..KSPLIT-1
    int b  = blockIdx.y;

    __shared__ __align__(16) float sh_t[M_ * STR];
    __shared__ __align__(16) float sh_p[N_ * STR];
    __shared__ __align__(16) float sh_g[N_ * STR];

    int tid = threadIdx.x;
    int mg = tid % 10;        // m0 = mg*5
    int ng = tid / 10;        // 0..49 active; n0 = ng*2
    bool active = tid < 500;
    int m0 = mg * 5;
    int n0 = ng * 2;

    const float* Tbase = tmask + (size_t)b * M_ * HW;
    const float* Pbase = g_P + (size_t)b * N_ * HW;
    const float* Gbase = g_G + (size_t)b * N_ * HW;

    ull a1[5][2], a2[5][2];
    #pragma unroll
    for (int i = 0; i < 5; i++)
        #pragma unroll
        for (int j = 0; j < 2; j++) { a1[i][j] = 0ULL; a2[i][j] = 0ULL; }

    const ull* sh_t2 = (const ull*)sh_t;
    const ull* sh_p2 = (const ull*)sh_p;
    const ull* sh_g2 = (const ull*)sh_g;

    int kbeg = ks * KCHUNK;
    for (int k0 = kbeg; k0 < kbeg + KCHUNK; k0 += KK) {
        // T: 50 rows x 8 float4 = 400; P,G: 100 rows x 8 float4 = 800 each
        #pragma unroll
        for (int e = tid; e < 400; e += 512) {
            int row = e >> 3, c4 = (e & 7) << 2;
            float4 v = *(const float4*)(Tbase + (size_t)row * HW + k0 + c4);
            float* d = sh_t + row * STR + c4;
            *(float2*)(d)     = make_float2(v.x, v.y);
            *(float2*)(d + 2) = make_float2(v.z, v.w);
        }
        #pragma unroll
        for (int e = tid; e < 800; e += 512) {
            int row = e >> 3, c4 = (e & 7) << 2;
            float4 v = *(const float4*)(Pbase + (size_t)row * HW + k0 + c4);
            float* d = sh_p + row * STR + c4;
            *(float2*)(d)     = make_float2(v.x, v.y);
            *(float2*)(d + 2) = make_float2(v.z, v.w);
            float4 w = *(const float4*)(Gbase + (size_t)row * HW + k0 + c4);
            float* d2 = sh_g + row * STR + c4;
            *(float2*)(d2)     = make_float2(w.x, w.y);
            *(float2*)(d2 + 2) = make_float2(w.z, w.w);
        }
        __syncthreads();

        if (active) {
            #pragma unroll
            for (int kp = 0; kp < KK / 2; kp++) {
                ull tv[5], pv[2], gv[2];
                #pragma unroll
                for (int i = 0; i < 5; i++) tv[i] = sh_t2[(m0 + i) * (STR / 2) + kp];
                #pragma unroll
                for (int j = 0; j < 2; j++) {
                    pv[j] = sh_p2[(n0 + j) * (STR / 2) + kp];
                    gv[j] = sh_g2[(n0 + j) * (STR / 2) + kp];
                }
                #pragma unroll
                for (int i = 0; i < 5; i++) {
                    #pragma unroll
                    for (int j = 0; j < 2; j++) {
                        FMA2(a1[i][j], tv[i], pv[j], a1[i][j]);
                        FMA2(a2[i][j], tv[i], gv[j], a2[i][j]);
                    }
                }
            }
        }
        __syncthreads();
    }

    if (active) {
        #pragma unroll
        for (int i = 0; i < 5; i++) {
            #pragma unroll
            for (int j = 0; j < 2; j++) {
                int n = n0 + j;
                int m = m0 + i;
                size_t idx = ((size_t)(b * N_ + n) * M_ + m) * KSPLIT + ks;
                float2 v1 = *(float2*)&a1[i][j];
                float2 v2 = *(float2*)&a2[i][j];
                g_part1[idx] = v1.x + v1.y;
                g_part2[idx] = v2.x + v2.y;
            }
        }
    }
}

// ---------------- kernel 4: assemble (ks-contiguous vector reduce) ---------
__global__ void k_assemble(const float* __restrict__ pred_prob,
                           const float* __restrict__ pred_mom,
                           const int*   __restrict__ tcls,
                           const float* __restrict__ tmom,
                           float* __restrict__ out) {
    int idx = blockIdx.x * blockDim.x + threadIdx.x;
    if (idx >= B_ * N_ * M_) return;
    int m = idx % M_;
    int n = (idx / M_) % N_;
    int b = idx / (N_ * M_);

    int cls = tcls[b * M_ + m];
    if (cls <= 0) { out[idx] = 100000.0f; return; }

    size_t base = (size_t)idx * KSPLIT;
    const float4* p1 = (const float4*)(g_part1 + base);
    const float4* p2 = (const float4*)(g_part2 + base);
    float dot1 = 0.f, dot2 = 0.f;
    #pragma unroll
    for (int ks = 0; ks < KSPLIT / 4; ks++) {
        float4 v = p1[ks];
        float4 w = p2[ks];
        dot1 += (v.x + v.y) + (v.z + v.w);
        dot2 += (w.x + w.y) + (w.z + w.w);
    }

    float Sp = g_Sp[b * N_ + n];
    float F0s = g_F0[b * N_ + n];
    float St = g_St[b * M_ + m];
    float pos = Sp + St;
    float cost_dice = 1.0f - 2.0f * dot1 / (pos + 0.001f);
    float cost_focal = (F0s + dot2) * (1.0f / (float)HW);
    float cost_class = -pred_prob[((size_t)b * C_ + cls) * N_ + n];

    const float* pmv = pred_mom + (size_t)(b * N_ + n) * 4;
    float p0 = __expf(fminf(pmv[0], 10.0f));
    float p1f = TWO_PI_F / (1.0f + __expf(-pmv[1]));
    float p2f = TWO_PI_F / (1.0f + __expf(-pmv[2]));
    float p3 = __expf(fminf(pmv[3], 10.0f));
    const float* tmv = tmom + (size_t)(b * M_ + m) * 4;
    float t0 = tmv[0], t1 = tmv[1], t2 = tmv[2], t3 = tmv[3];

    float pe = (t2 - p2f > PI_F) ? TWO_PI_F : 0.0f;
    float te = (p2f - t2 > PI_F) ? TWO_PI_F : 0.0f;
    float l1 = (fabsf(p0 / (t0 + 0.001f) - 1.0f)
              + fabsf(p1f / (t1 + 0.001f) - 1.0f)
              + fabsf((p2f + pe) / (t2 + te + 0.001f) - 1.0f)
              + fabsf(p3 / (t3 + 0.001f) - 1.0f)) * 0.25f;

    float w1 = p0, x1 = p1f, y1 = p2f, h1 = p3;
    float w2 = t0, x2 = t1, y2 = t2, h2 = t3;
    float y1e = (y2 - y1 > PI_F) ? TWO_PI_F : 0.0f;
    float y2e = (y1 - y2 > PI_F) ? TWO_PI_F : 0.0f;
    y1 += y1e;
    y2 += y2e;
    float r1 = x1 + w1 * 0.5f, l1b = x1 - w1 * 0.5f;
    float r2 = x2 + w2 * 0.5f, l2b = x2 - w2 * 0.5f;
    float u1 = y1 + h1 * 0.5f, d1 = y1 - h1 * 0.5f;
    float u2 = y2 + h2 * 0.5f, d2 = y2 - h2 * 0.5f;
    float w = fminf(r1, r2) - fmaxf(l1b, l2b);
    float h = fminf(u1, u2) - fmaxf(d1, d2);
    float iou = (w > 0.0f && h > 0.0f)
                ? (w * h) / (w1 * h1 + w2 * h2 - w * h + 0.001f) : 0.0f;
    float cw = fmaxf(r1, r2) - fminf(l1b, l2b);
    float ch = fmaxf(u1, u2) - fminf(d1, d2);
    float cw2 = cw * cw, ch2 = ch * ch;
    float dw = w1 - w2, dh = h1 - h2;
    float rho_w = dw * dw / (cw2 + 0.001f);
    float rho_h = dh * dh / (ch2 + 0.001f);
    float dx = x1 - x2, dy = y1 - y2;
    float rho_d = (dx * dx + dy * dy) / (cw2 + ch2 + 0.001f);
    float ce = 1.0f - iou + rho_d + rho_w + rho_h;

    out[idx] = 0.25f * cost_focal + 0.75f * cost_dice + cost_class
             + 0.8f * l1 + 0.2f * ce;
}

extern "C" void kernel_launch(void* const* d_in, const int* in_sizes, int n_in,
                              void* d_out, int out_size) {
    const float* pred_prob = (const float*)d_in[0];
    const float* pred_mask = (const float*)d_in[1];
    const float* pred_mom  = (const float*)d_in[2];
    const int*   tcls      = (const int*)d_in[3];
    const float* tmask     = (const float*)d_in[4];
    const float* tmom      = (const float*)d_in[5];
    float* out = (float*)d_out;

    k_resize<<<B_ * N_, 256>>>(pred_mask);
    k_st<<<B_ * M_, 256>>>(tmask);
    dim3 grid(KSPLIT, B_);
    k_dots<<<grid, 512>>>(tmask);
    k_assemble<<<(B_ * N_ * M_ + 255) / 256, 256>>>(pred_prob, pred_mom, tcls, tmom, out);
}

// round 6
// speedup vs baseline: 2.3207x; 1.1159x over previous
#include <cuda_runtime.h>
#include <math.h>

#define B_ 2
#define C_ 10
#define N_ 100
#define M_ 50
#define HW 9216      // 96*96
#define HPWP 576     // 24*24
#define KSPLIT 72
#define KCHUNK 128   // 9216/72
#define KK 32        // k-stage in shared
#define STR 34       // row stride (floats): 8B-aligned rows, conflict-free LDS.64
#define TWO_PI_F 6.2831854820251465f
#define PI_F 3.1415927410125732f

typedef unsigned long long ull;

// ---------------- scratch ----------------
__device__ __align__(16) float g_P[B_ * N_ * HW];
__device__ __align__(16) float g_G[B_ * N_ * HW];
__device__ __align__(16) float g_Sp4[B_ * N_ * 4];   // per-quarter partial sums
__device__ __align__(16) float g_F04[B_ * N_ * 4];
__device__ __align__(16) float g_St[B_ * M_];
// layout: [b][n][m][ks]  (ks contiguous)
__device__ __align__(16) float g_part1[B_ * N_ * M_ * KSPLIT];
__device__ __align__(16) float g_part2[B_ * N_ * M_ * KSPLIT];

#define FMA2(d, a, b, c) \
    asm("fma.rn.f32x2 %0, %1, %2, %3;" : "=l"(d) : "l"(a), "l"(b), "l"(c))

// ---------------- helpers ----------------
__device__ __forceinline__ float blockReduceSum(float v, float* sh) {
    int lane = threadIdx.x & 31;
    int wid = threadIdx.x >> 5;
    #pragma unroll
    for (int o = 16; o > 0; o >>= 1) v += __shfl_down_sync(0xffffffffu, v, o);
    if (lane == 0) sh[wid] = v;
    __syncthreads();
    v = (threadIdx.x < 8) ? sh[threadIdx.x] : 0.0f;
    if (wid == 0) {
        #pragma unroll
        for (int o = 4; o > 0; o >>= 1) v += __shfl_down_sync(0xffffffffu, v, o);
    }
    return v;
}

// ------ kernel A: fused resize(4-way split per (b,n)) + St ------
// blocks 0..799: resize chunk q of (b,n);  blocks 800..899: St for (b,m)
__global__ void k_pre(const float* __restrict__ pred_mask,
                      const float* __restrict__ tmask) {
    __shared__ float sm[HPWP];
    __shared__ float red[8];
    int tid = threadIdx.x;

    if (blockIdx.x < 800) {
        int bc = blockIdx.x;
        int bn = bc >> 2;        // 0..199
        int q  = bc & 3;         // row-chunk 0..3 (24 output rows each)
        const float* src = pred_mask + bn * HPWP;
        for (int i = tid; i < HPWP; i += 256) sm[i] = src[i];
        __syncthreads();

        float* Pout = g_P + (size_t)bn * HW;
        float* Gout = g_G + (size_t)bn * HW;
        float sp = 0.0f, sf0 = 0.0f;
        int base = q * 2304;

        for (int r = tid; r < 2304; r += 256) {
            int i = base + r;
            int y = i / 96, x = i - y * 96;
            float sy = y * 0.25f - 0.375f;
            float sx = x * 0.25f - 0.375f;
            float fy = floorf(sy), fx = floorf(sx);
            float wy = sy - fy, wx = sx - fx;
            int iy = (int)fy, ix = (int)fx;
            int iy0 = max(iy, 0), iy1 = min(iy + 1, 23);
            int ix0 = max(ix, 0), ix1 = min(ix + 1, 23);
            float v00 = sm[iy0 * 24 + ix0], v01 = sm[iy0 * 24 + ix1];
            float v10 = sm[iy1 * 24 + ix0], v11 = sm[iy1 * 24 + ix1];
            float top = v00 + wx * (v01 - v00);
            float bot = v10 + wx * (v11 - v10);
            float p = top + wy * (bot - top);

            float pc = fminf(fmaxf(p, 0.001f), 0.999f);
            float omc = 1.0f - pc;
            float f1 = 0.25f * (-__logf(pc)) * omc * omc;
            float f0 = 0.75f * (-__logf(omc)) * pc * pc;
            Pout[i] = p;
            Gout[i] = f1 - f0;
            sp += fabsf(p);
            sf0 += f0;
        }
        float tsp = blockReduceSum(sp, red);
        __syncthreads();
        float tsf = blockReduceSum(sf0, red);
        if (tid == 0) {
            g_Sp4[bn * 4 + q] = tsp;
            g_F04[bn * 4 + q] = tsf;
        }
    } else {
        int bm = blockIdx.x - 800;   // 0..99
        const float4* src = (const float4*)(tmask + (size_t)bm * HW);
        float s = 0.0f;
        for (int i = tid; i < HW / 4; i += 256) {
            float4 v = src[i];
            s += (fabsf(v.x) + fabsf(v.y)) + (fabsf(v.z) + fabsf(v.w));
        }
        float t = blockReduceSum(s, red);
        if (tid == 0) g_St[bm] = t;
    }
}

// ---------------- kernel B: dots, 512 threads, all-N per block -------------
__global__ void __launch_bounds__(512) k_dots(const float* __restrict__ tmask) {
    int ks = blockIdx.x;   // 0..KSPLIT-1
    int b  = blockIdx.y;

    __shared__ __align__(16) float sh_t[M_ * STR];
    __shared__ __align__(16) float sh_p[N_ * STR];
    __shared__ __align__(16) float sh_g[N_ * STR];

    int tid = threadIdx.x;
    int mg = tid % 10;        // m0 = mg*5
    int ng = tid / 10;        // 0..49 active; n0 = ng*2
    bool active = tid < 500;
    int m0 = mg * 5;
    int n0 = ng * 2;

    const float* Tbase = tmask + (size_t)b * M_ * HW;
    const float* Pbase = g_P + (size_t)b * N_ * HW;
    const float* Gbase = g_G + (size_t)b * N_ * HW;

    ull a1[5][2], a2[5][2];
    #pragma unroll
    for (int i = 0; i < 5; i++)
        #pragma unroll
        for (int j = 0; j < 2; j++) { a1[i][j] = 0ULL; a2[i][j] = 0ULL; }

    const ull* sh_t2 = (const ull*)sh_t;
    const ull* sh_p2 = (const ull*)sh_p;
    const ull* sh_g2 = (const ull*)sh_g;

    int kbeg = ks * KCHUNK;
    for (int k0 = kbeg; k0 < kbeg + KCHUNK; k0 += KK) {
        #pragma unroll
        for (int e = tid; e < 400; e += 512) {
            int row = e >> 3, c4 = (e & 7) << 2;
            float4 v = *(const float4*)(Tbase + (size_t)row * HW + k0 + c4);
            float* d = sh_t + row * STR + c4;
            *(float2*)(d)     = make_float2(v.x, v.y);
            *(float2*)(d + 2) = make_float2(v.z, v.w);
        }
        #pragma unroll
        for (int e = tid; e < 800; e += 512) {
            int row = e >> 3, c4 = (e & 7) << 2;
            float4 v = *(const float4*)(Pbase + (size_t)row * HW + k0 + c4);
            float* d = sh_p + row * STR + c4;
            *(float2*)(d)     = make_float2(v.x, v.y);
            *(float2*)(d + 2) = make_float2(v.z, v.w);
            float4 w = *(const float4*)(Gbase + (size_t)row * HW + k0 + c4);
            float* d2 = sh_g + row * STR + c4;
            *(float2*)(d2)     = make_float2(w.x, w.y);
            *(float2*)(d2 + 2) = make_float2(w.z, w.w);
        }
        __syncthreads();

        if (active) {
            #pragma unroll
            for (int kp = 0; kp < KK / 2; kp++) {
                ull tv[5], pv[2], gv[2];
                #pragma unroll
                for (int i = 0; i < 5; i++) tv[i] = sh_t2[(m0 + i) * (STR / 2) + kp];
                #pragma unroll
                for (int j = 0; j < 2; j++) {
                    pv[j] = sh_p2[(n0 + j) * (STR / 2) + kp];
                    gv[j] = sh_g2[(n0 + j) * (STR / 2) + kp];
                }
                #pragma unroll
                for (int i = 0; i < 5; i++) {
                    #pragma unroll
                    for (int j = 0; j < 2; j++) {
                        FMA2(a1[i][j], tv[i], pv[j], a1[i][j]);
                        FMA2(a2[i][j], tv[i], gv[j], a2[i][j]);
                    }
                }
            }
        }
        __syncthreads();
    }

    if (active) {
        #pragma unroll
        for (int i = 0; i < 5; i++) {
            #pragma unroll
            for (int j = 0; j < 2; j++) {
                int n = n0 + j;
                int m = m0 + i;
                size_t idx = ((size_t)(b * N_ + n) * M_ + m) * KSPLIT + ks;
                float2 v1 = *(float2*)&a1[i][j];
                float2 v2 = *(float2*)&a2[i][j];
                g_part1[idx] = v1.x + v1.y;
                g_part2[idx] = v2.x + v2.y;
            }
        }
    }
}

// ---------------- kernel C: assemble, 2 threads per output -----------------
__global__ void k_assemble(const float* __restrict__ pred_prob,
                           const float* __restrict__ pred_mom,
                           const int*   __restrict__ tcls,
                           const float* __restrict__ tmom,
                           float* __restrict__ out) {
    int gid = blockIdx.x * blockDim.x + threadIdx.x;
    int oid = gid >> 1;
    int part = gid & 1;
    bool valid = oid < B_ * N_ * M_;
    int o = valid ? oid : 0;
    int m = o % M_;
    int n = (o / M_) % N_;
    int b = o / (N_ * M_);

    // each half-thread reduces 36 ks (9 float4 per array)
    size_t base = (size_t)o * KSPLIT + part * (KSPLIT / 2);
    const float4* p1 = (const float4*)(g_part1 + base);
    const float4* p2 = (const float4*)(g_part2 + base);
    float dot1 = 0.f, dot2 = 0.f;
    #pragma unroll
    for (int i = 0; i < KSPLIT / 8; i++) {
        float4 v = p1[i];
        float4 w = p2[i];
        dot1 += (v.x + v.y) + (v.z + v.w);
        dot2 += (w.x + w.y) + (w.z + w.w);
    }
    dot1 += __shfl_down_sync(0xffffffffu, dot1, 1);
    dot2 += __shfl_down_sync(0xffffffffu, dot2, 1);

    if (!valid || part) return;

    int cls = tcls[b * M_ + m];
    if (cls <= 0) { out[oid] = 100000.0f; return; }

    const float4 sp4 = *(const float4*)(g_Sp4 + (b * N_ + n) * 4);
    const float4 f04 = *(const float4*)(g_F04 + (b * N_ + n) * 4);
    float Sp = (sp4.x + sp4.y) + (sp4.z + sp4.w);
    float F0s = (f04.x + f04.y) + (f04.z + f04.w);
    float St = g_St[b * M_ + m];
    float pos = Sp + St;
    float cost_dice = 1.0f - 2.0f * dot1 / (pos + 0.001f);
    float cost_focal = (F0s + dot2) * (1.0f / (float)HW);
    float cost_class = -pred_prob[((size_t)b * C_ + cls) * N_ + n];

    const float* pmv = pred_mom + (size_t)(b * N_ + n) * 4;
    float p0 = __expf(fminf(pmv[0], 10.0f));
    float p1f = TWO_PI_F / (1.0f + __expf(-pmv[1]));
    float p2f = TWO_PI_F / (1.0f + __expf(-pmv[2]));
    float p3 = __expf(fminf(pmv[3], 10.0f));
    const float* tmv = tmom + (size_t)(b * M_ + m) * 4;
    float t0 = tmv[0], t1 = tmv[1], t2 = tmv[2], t3 = tmv[3];

    float pe = (t2 - p2f > PI_F) ? TWO_PI_F : 0.0f;
    float te = (p2f - t2 > PI_F) ? TWO_PI_F : 0.0f;
    float l1 = (fabsf(p0 / (t0 + 0.001f) - 1.0f)
              + fabsf(p1f / (t1 + 0.001f) - 1.0f)
              + fabsf((p2f + pe) / (t2 + te + 0.001f) - 1.0f)
              + fabsf(p3 / (t3 + 0.001f) - 1.0f)) * 0.25f;

    float w1 = p0, x1 = p1f, y1 = p2f, h1 = p3;
    float w2 = t0, x2 = t1, y2 = t2, h2 = t3;
    float y1e = (y2 - y1 > PI_F) ? TWO_PI_F : 0.0f;
    float y2e = (y1 - y2 > PI_F) ? TWO_PI_F : 0.0f;
    y1 += y1e;
    y2 += y2e;
    float r1 = x1 + w1 * 0.5f, l1b = x1 - w1 * 0.5f;
    float r2 = x2 + w2 * 0.5f, l2b = x2 - w2 * 0.5f;
    float u1 = y1 + h1 * 0.5f, d1 = y1 - h1 * 0.5f;
    float u2 = y2 + h2 * 0.5f, d2 = y2 - h2 * 0.5f;
    float w = fminf(r1, r2) - fmaxf(l1b, l2b);
    float h = fminf(u1, u2) - fmaxf(d1, d2);
    float iou = (w > 0.0f && h > 0.0f)
                ? (w * h) / (w1 * h1 + w2 * h2 - w * h + 0.001f) : 0.0f;
    float cw = fmaxf(r1, r2) - fminf(l1b, l2b);
    float ch = fmaxf(u1, u2) - fminf(d1, d2);
    float cw2 = cw * cw, ch2 = ch * ch;
    float dw = w1 - w2, dh = h1 - h2;
    float rho_w = dw * dw / (cw2 + 0.001f);
    float rho_h = dh * dh / (ch2 + 0.001f);
    float dx = x1 - x2, dy = y1 - y2;
    float rho_d = (dx * dx + dy * dy) / (cw2 + ch2 + 0.001f);
    float ce = 1.0f - iou + rho_d + rho_w + rho_h;

    out[oid] = 0.25f * cost_focal + 0.75f * cost_dice + cost_class
             + 0.8f * l1 + 0.2f * ce;
}

extern "C" void kernel_launch(void* const* d_in, const int* in_sizes, int n_in,
                              void* d_out, int out_size) {
    const float* pred_prob = (const float*)d_in[0];
    const float* pred_mask = (const float*)d_in[1];
    const float* pred_mom  = (const float*)d_in[2];
    const int*   tcls      = (const int*)d_in[3];
    const float* tmask     = (const float*)d_in[4];
    const float* tmom      = (const float*)d_in[5];
    float* out = (float*)d_out;

    k_pre<<<900, 256>>>(pred_mask, tmask);
    dim3 grid(KSPLIT, B_);
    k_dots<<<grid, 512>>>(tmask);
    int total_threads = 2 * B_ * N_ * M_;
    k_assemble<<<(total_threads + 255) / 256, 256>>>(pred_prob, pred_mom, tcls, tmom, out);
}

// round 7
// speedup vs baseline: 2.6494x; 1.1417x over previous
#include <cuda_runtime.h>
#include <math.h>

#define B_ 2
#define C_ 10
#define N_ 100
#define M_ 50
#define HW 9216      // 96*96
#define HPWP 576     // 24*24
#define KSPLIT 72
#define KCHUNK 128   // 9216/72
#define KK 32        // k-stage in shared
#define STR 34       // row stride (floats): 8B rows, conflict-free LDS.64
#define BUF_FLOATS ((M_ + 2 * N_) * STR)   // 8500 floats = 34000 B per buffer
#define TWO_PI_F 6.2831854820251465f
#define PI_F 3.1415927410125732f

typedef unsigned long long ull;

// ---------------- scratch ----------------
__device__ __align__(16) float g_P[B_ * N_ * HW];
__device__ __align__(16) float g_G[B_ * N_ * HW];
__device__ __align__(16) float g_Sp4[B_ * N_ * 4];
__device__ __align__(16) float g_F04[B_ * N_ * 4];
__device__ __align__(16) float g_St[B_ * M_];
// layout: [b][n][m][ks]  (ks contiguous)
__device__ __align__(16) float g_part1[B_ * N_ * M_ * KSPLIT];
__device__ __align__(16) float g_part2[B_ * N_ * M_ * KSPLIT];

__constant__ float c_w[4] = {0.625f, 0.875f, 0.125f, 0.375f};

#define FMA2(d, a, b, c) \
    asm("fma.rn.f32x2 %0, %1, %2, %3;" : "=l"(d) : "l"(a), "l"(b), "l"(c))

// ---------------- helpers ----------------
__device__ __forceinline__ float blockReduceSum(float v, float* sh) {
    int lane = threadIdx.x & 31;
    int wid = threadIdx.x >> 5;
    #pragma unroll
    for (int o = 16; o > 0; o >>= 1) v += __shfl_down_sync(0xffffffffu, v, o);
    if (lane == 0) sh[wid] = v;
    __syncthreads();
    v = (threadIdx.x < 8) ? sh[threadIdx.x] : 0.0f;
    if (wid == 0) {
        #pragma unroll
        for (int o = 4; o > 0; o >>= 1) v += __shfl_down_sync(0xffffffffu, v, o);
    }
    return v;
}

// ------ kernel A: fused resize (4 px/step, fixed weights) + St ------
// blocks 0..799: resize chunk q of (b,n);  blocks 800..899: St for (b,m)
__global__ void k_pre(const float* __restrict__ pred_mask,
                      const float* __restrict__ tmask) {
    __shared__ float sm[HPWP];
    __shared__ float red[8];
    int tid = threadIdx.x;

    if (blockIdx.x < 800) {
        int bc = blockIdx.x;
        int bn = bc >> 2;        // 0..199
        int q  = bc & 3;         // 24-row chunk
        const float* src = pred_mask + bn * HPWP;
        for (int i = tid; i < HPWP; i += 256) sm[i] = src[i];
        __syncthreads();

        float* Pout = g_P + (size_t)bn * HW + q * 2304;
        float* Gout = g_G + (size_t)bn * HW + q * 2304;
        float sp = 0.0f, sf0 = 0.0f;

        #pragma unroll
        for (int it = 0; it < 3; it++) {
            int g = tid + (it << 8);     // 4-px group id, 0..575
            if (g < 576) {
                int y = g / 24;          // local row 0..23
                int j = g - y * 24;      // x-group 0..23
                int yg = q * 24 + y;     // global output row
                int iy = (yg - 2) >> 2;
                float wy = c_w[yg & 3];
                int iy0 = max(iy, 0) * 24, iy1 = min(iy + 1, 23) * 24;
                int cm = max(j - 1, 0), cp = min(j + 1, 23);

                float a0 = sm[iy0 + cm], a1 = sm[iy0 + j], a2 = sm[iy0 + cp];
                float b0 = sm[iy1 + cm], b1 = sm[iy1 + j], b2 = sm[iy1 + cp];

                float t0 = a0 + 0.625f * (a1 - a0);
                float t1 = a0 + 0.875f * (a1 - a0);
                float t2 = a1 + 0.125f * (a2 - a1);
                float t3 = a1 + 0.375f * (a2 - a1);
                float u0 = b0 + 0.625f * (b1 - b0);
                float u1 = b0 + 0.875f * (b1 - b0);
                float u2 = b1 + 0.125f * (b2 - b1);
                float u3 = b1 + 0.375f * (b2 - b1);

                float p0 = t0 + wy * (u0 - t0);
                float p1 = t1 + wy * (u1 - t1);
                float p2 = t2 + wy * (u2 - t2);
                float p3 = t3 + wy * (u3 - t3);

                float gv[4], pv[4] = {p0, p1, p2, p3};
                #pragma unroll
                for (int r = 0; r < 4; r++) {
                    float p = pv[r];
                    float pc = fminf(fmaxf(p, 0.001f), 0.999f);
                    float omc = 1.0f - pc;
                    float f1 = 0.25f * (-__logf(pc)) * omc * omc;
                    float f0 = 0.75f * (-__logf(omc)) * pc * pc;
                    gv[r] = f1 - f0;
                    sp += fabsf(p);
                    sf0 += f0;
                }
                int o = y * 96 + j * 4;
                *(float4*)(Pout + o) = make_float4(p0, p1, p2, p3);
                *(float4*)(Gout + o) = make_float4(gv[0], gv[1], gv[2], gv[3]);
            }
        }
        float tsp = blockReduceSum(sp, red);
        __syncthreads();
        float tsf = blockReduceSum(sf0, red);
        if (tid == 0) {
            g_Sp4[bn * 4 + q] = tsp;
            g_F04[bn * 4 + q] = tsf;
        }
    } else {
        int bm = blockIdx.x - 800;   // 0..99
        const float4* src = (const float4*)(tmask + (size_t)bm * HW);
        float s = 0.0f;
        for (int i = tid; i < HW / 4; i += 256) {
            float4 v = src[i];
            s += (fabsf(v.x) + fabsf(v.y)) + (fabsf(v.z) + fabsf(v.w));
        }
        float t = blockReduceSum(s, red);
        if (tid == 0) g_St[bm] = t;
    }
}

// ---------------- kernel B: dots, double-buffered smem ----------------
__global__ void __launch_bounds__(512) k_dots(const float* __restrict__ tmask) {
    extern __shared__ __align__(16) float dsm[];
    int ks = blockIdx.x;
    int b  = blockIdx.y;

    int tid = threadIdx.x;
    int mg = tid % 10;
    int ng = tid / 10;        // 0..49 active
    bool active = tid < 500;
    int m0 = mg * 5;
    int n0 = ng * 2;

    const float* Tbase = tmask + (size_t)b * M_ * HW;
    const float* Pbase = g_P + (size_t)b * N_ * HW;
    const float* Gbase = g_G + (size_t)b * N_ * HW;

    ull a1[5][2], a2[5][2];
    #pragma unroll
    for (int i = 0; i < 5; i++)
        #pragma unroll
        for (int j = 0; j < 2; j++) { a1[i][j] = 0ULL; a2[i][j] = 0ULL; }

    int row0 = tid >> 3, c40 = (tid & 7) << 2;
    int e1 = tid + 512;
    int row1 = e1 >> 3, c41 = (e1 & 7) << 2;

    float4 ft, fp0, fg0, fp1, fg1;
    int kbeg = ks * KCHUNK;

    // prefetch stage 0
    {
        int k0 = kbeg;
        if (tid < 400) ft = *(const float4*)(Tbase + (size_t)row0 * HW + k0 + c40);
        fp0 = *(const float4*)(Pbase + (size_t)row0 * HW + k0 + c40);
        fg0 = *(const float4*)(Gbase + (size_t)row0 * HW + k0 + c40);
        if (tid < 288) {
            fp1 = *(const float4*)(Pbase + (size_t)row1 * HW + k0 + c41);
            fg1 = *(const float4*)(Gbase + (size_t)row1 * HW + k0 + c41);
        }
        float* bt = dsm;
        float* bp = bt + M_ * STR;
        float* bg = bp + N_ * STR;
        if (tid < 400) {
            float* d = bt + row0 * STR + c40;
            *(float2*)(d) = make_float2(ft.x, ft.y);
            *(float2*)(d + 2) = make_float2(ft.z, ft.w);
        }
        {
            float* d = bp + row0 * STR + c40;
            *(float2*)(d) = make_float2(fp0.x, fp0.y);
            *(float2*)(d + 2) = make_float2(fp0.z, fp0.w);
            float* d2 = bg + row0 * STR + c40;
            *(float2*)(d2) = make_float2(fg0.x, fg0.y);
            *(float2*)(d2 + 2) = make_float2(fg0.z, fg0.w);
        }
        if (tid < 288) {
            float* d = bp + row1 * STR + c41;
            *(float2*)(d) = make_float2(fp1.x, fp1.y);
            *(float2*)(d + 2) = make_float2(fp1.z, fp1.w);
            float* d2 = bg + row1 * STR + c41;
            *(float2*)(d2) = make_float2(fg1.x, fg1.y);
            *(float2*)(d2 + 2) = make_float2(fg1.z, fg1.w);
        }
    }
    __syncthreads();

    #pragma unroll
    for (int s = 0; s < KCHUNK / KK; s++) {
        int cur = s & 1;
        // issue next stage's LDGs before compute
        if (s < KCHUNK / KK - 1) {
            int k0 = kbeg + (s + 1) * KK;
            if (tid < 400) ft = *(const float4*)(Tbase + (size_t)row0 * HW + k0 + c40);
            fp0 = *(const float4*)(Pbase + (size_t)row0 * HW + k0 + c40);
            fg0 = *(const float4*)(Gbase + (size_t)row0 * HW + k0 + c40);
            if (tid < 288) {
                fp1 = *(const float4*)(Pbase + (size_t)row1 * HW + k0 + c41);
                fg1 = *(const float4*)(Gbase + (size_t)row1 * HW + k0 + c41);
            }
        }

        // compute on current buffer
        {
            const float* bt = dsm + cur * BUF_FLOATS;
            const ull* sh_t2 = (const ull*)bt;
            const ull* sh_p2 = (const ull*)(bt + M_ * STR);
            const ull* sh_g2 = (const ull*)(bt + M_ * STR + N_ * STR);
            if (active) {
                #pragma unroll
                for (int kp = 0; kp < KK / 2; kp++) {
                    ull tv[5], pv[2], gv[2];
                    #pragma unroll
                    for (int i = 0; i < 5; i++) tv[i] = sh_t2[(m0 + i) * (STR / 2) + kp];
                    #pragma unroll
                    for (int j = 0; j < 2; j++) {
                        pv[j] = sh_p2[(n0 + j) * (STR / 2) + kp];
                        gv[j] = sh_g2[(n0 + j) * (STR / 2) + kp];
                    }
                    #pragma unroll
                    for (int i = 0; i < 5; i++) {
                        #pragma unroll
                        for (int j = 0; j < 2; j++) {
                            FMA2(a1[i][j], tv[i], pv[j], a1[i][j]);
                            FMA2(a2[i][j], tv[i], gv[j], a2[i][j]);
                        }
                    }
                }
            }
        }

        // commit prefetched data to the other buffer
        if (s < KCHUNK / KK - 1) {
            float* bt = dsm + (cur ^ 1) * BUF_FLOATS;
            float* bp = bt + M_ * STR;
            float* bg = bp + N_ * STR;
            if (tid < 400) {
                float* d = bt + row0 * STR + c40;
                *(float2*)(d) = make_float2(ft.x, ft.y);
                *(float2*)(d + 2) = make_float2(ft.z, ft.w);
            }
            {
                float* d = bp + row0 * STR + c40;
                *(float2*)(d) = make_float2(fp0.x, fp0.y);
                *(float2*)(d + 2) = make_float2(fp0.z, fp0.w);
                float* d2 = bg + row0 * STR + c40;
                *(float2*)(d2) = make_float2(fg0.x, fg0.y);
                *(float2*)(d2 + 2) = make_float2(fg0.z, fg0.w);
            }
            if (tid < 288) {
                float* d = bp + row1 * STR + c41;
                *(float2*)(d) = make_float2(fp1.x, fp1.y);
                *(float2*)(d + 2) = make_float2(fp1.z, fp1.w);
                float* d2 = bg + row1 * STR + c41;
                *(float2*)(d2) = make_float2(fg1.x, fg1.y);
                *(float2*)(d2 + 2) = make_float2(fg1.z, fg1.w);
            }
        }
        __syncthreads();
    }

    if (active) {
        #pragma unroll
        for (int i = 0; i < 5; i++) {
            #pragma unroll
            for (int j = 0; j < 2; j++) {
                int n = n0 + j;
                int m = m0 + i;
                size_t idx = ((size_t)(b * N_ + n) * M_ + m) * KSPLIT + ks;
                float2 v1 = *(float2*)&a1[i][j];
                float2 v2 = *(float2*)&a2[i][j];
                g_part1[idx] = v1.x + v1.y;
                g_part2[idx] = v2.x + v2.y;
            }
        }
    }
}

// ---------------- kernel C: assemble, 2 threads per output -----------------
__global__ void k_assemble(const float* __restrict__ pred_prob,
                           const float* __restrict__ pred_mom,
                           const int*   __restrict__ tcls,
                           const float* __restrict__ tmom,
                           float* __restrict__ out) {
    int gid = blockIdx.x * blockDim.x + threadIdx.x;
    int oid = gid >> 1;
    int part = gid & 1;
    bool valid = oid < B_ * N_ * M_;
    int o = valid ? oid : 0;
    int m = o % M_;
    int n = (o / M_) % N_;
    int b = o / (N_ * M_);

    size_t base = (size_t)o * KSPLIT + part * (KSPLIT / 2);
    const float4* p1 = (const float4*)(g_part1 + base);
    const float4* p2 = (const float4*)(g_part2 + base);
    float dot1 = 0.f, dot2 = 0.f;
    #pragma unroll
    for (int i = 0; i < KSPLIT / 8; i++) {
        float4 v = p1[i];
        float4 w = p2[i];
        dot1 += (v.x + v.y) + (v.z + v.w);
        dot2 += (w.x + w.y) + (w.z + w.w);
    }
    dot1 += __shfl_down_sync(0xffffffffu, dot1, 1);
    dot2 += __shfl_down_sync(0xffffffffu, dot2, 1);

    if (!valid || part) return;

    int cls = tcls[b * M_ + m];
    if (cls <= 0) { out[oid] = 100000.0f; return; }

    const float4 sp4 = *(const float4*)(g_Sp4 + (b * N_ + n) * 4);
    const float4 f04 = *(const float4*)(g_F04 + (b * N_ + n) * 4);
    float Sp = (sp4.x + sp4.y) + (sp4.z + sp4.w);
    float F0s = (f04.x + f04.y) + (f04.z + f04.w);
    float St = g_St[b * M_ + m];
    float pos = Sp + St;
    float cost_dice = 1.0f - 2.0f * dot1 / (pos + 0.001f);
    float cost_focal = (F0s + dot2) * (1.0f / (float)HW);
    float cost_class = -pred_prob[((size_t)b * C_ + cls) * N_ + n];

    const float* pmv = pred_mom + (size_t)(b * N_ + n) * 4;
    float p0 = __expf(fminf(pmv[0], 10.0f));
    float p1f = TWO_PI_F / (1.0f + __expf(-pmv[1]));
    float p2f = TWO_PI_F / (1.0f + __expf(-pmv[2]));
    float p3 = __expf(fminf(pmv[3], 10.0f));
    const float* tmv = tmom + (size_t)(b * M_ + m) * 4;
    float t0 = tmv[0], t1 = tmv[1], t2 = tmv[2], t3 = tmv[3];

    float pe = (t2 - p2f > PI_F) ? TWO_PI_F : 0.0f;
    float te = (p2f - t2 > PI_F) ? TWO_PI_F : 0.0f;
    float l1 = (fabsf(p0 / (t0 + 0.001f) - 1.0f)
              + fabsf(p1f / (t1 + 0.001f) - 1.0f)
              + fabsf((p2f + pe) / (t2 + te + 0.001f) - 1.0f)
              + fabsf(p3 / (t3 + 0.001f) - 1.0f)) * 0.25f;

    float w1 = p0, x1 = p1f, y1 = p2f, h1 = p3;
    float w2 = t0, x2 = t1, y2 = t2, h2 = t3;
    float y1e = (y2 - y1 > PI_F) ? TWO_PI_F : 0.0f;
    float y2e = (y1 - y2 > PI_F) ? TWO_PI_F : 0.0f;
    y1 += y1e;
    y2 += y2e;
    float r1 = x1 + w1 * 0.5f, l1b = x1 - w1 * 0.5f;
    float r2 = x2 + w2 * 0.5f, l2b = x2 - w2 * 0.5f;
    float u1 = y1 + h1 * 0.5f, d1 = y1 - h1 * 0.5f;
    float u2 = y2 + h2 * 0.5f, d2 = y2 - h2 * 0.5f;
    float w = fminf(r1, r2) - fmaxf(l1b, l2b);
    float h = fminf(u1, u2) - fmaxf(d1, d2);
    float iou = (w > 0.0f && h > 0.0f)
                ? (w * h) / (w1 * h1 + w2 * h2 - w * h + 0.001f) : 0.0f;
    float cw = fmaxf(r1, r2) - fminf(l1b, l2b);
    float ch = fmaxf(u1, u2) - fminf(d1, d2);
    float cw2 = cw * cw, ch2 = ch * ch;
    float dw = w1 - w2, dh = h1 - h2;
    float rho_w = dw * dw / (cw2 + 0.001f);
    float rho_h = dh * dh / (ch2 + 0.001f);
    float dx = x1 - x2, dy = y1 - y2;
    float rho_d = (dx * dx + dy * dy) / (cw2 + ch2 + 0.001f);
    float ce = 1.0f - iou + rho_d + rho_w + rho_h;

    out[oid] = 0.25f * cost_focal + 0.75f * cost_dice + cost_class
             + 0.8f * l1 + 0.2f * ce;
}

extern "C" void kernel_launch(void* const* d_in, const int* in_sizes, int n_in,
                              void* d_out, int out_size) {
    const float* pred_prob = (const float*)d_in[0];
    const float* pred_mask = (const float*)d_in[1];
    const float* pred_mom  = (const float*)d_in[2];
    const int*   tcls      = (const int*)d_in[3];
    const float* tmask     = (const float*)d_in[4];
    const float* tmom      = (const float*)d_in[5];
    float* out = (float*)d_out;

    int smem = 2 * BUF_FLOATS * sizeof(float);  // 68000 B
    cudaFuncSetAttribute(k_dots, cudaFuncAttributeMaxDynamicSharedMemorySize, smem);

    k_pre<<<900, 256>>>(pred_mask, tmask);
    dim3 grid(KSPLIT, B_);
    k_dots<<<grid, 512, smem>>>(tmask);
    int total_threads = 2 * B_ * N_ * M_;
    k_assemble<<<(total_threads + 255) / 256, 256>>>(pred_prob, pred_mom, tcls, tmom, out);
}